// round 8
// baseline (speedup 1.0000x reference)
#include <cuda_runtime.h>
#include <cuda_bf16.h>
#include <cstdint>

// MLPTokenizer: out[b,f,d] = sum_h gelu(x[b,f]*W1[f,h]+b1[f,h]) * W2[f,h,d] + b2[f,d]
// B=4096, F=100, H=96, D=192. fp32, exact GELU (erf).
//
// Persistent-CTA design: grid = #SMs, each CTA processes a contiguous chunk of
// the 3200 (feature, 128-row B-tile) tiles, f-major, so W2[f] (72KB) is staged
// into SMEM at most twice per CTA (cp.async, overlapped with the gelu phase).
// GEMM is register-blocked 8 rows x 3 float4 column-chunks per thread on
// packed fma.rn.f32x2 (sm_103a FFMA2). x for the next tile is
// register-prefetched under the GEMM.

#define B_TOTAL   4096
#define F_TOTAL   100
#define H_DIM     96
#define D_DIM     192
#define ROWS_PER_CTA 128
#define THREADS   256
#define N_BTILES  (B_TOTAL / ROWS_PER_CTA)   // 32
#define N_TILES   (F_TOTAL * N_BTILES)       // 3200

#define SW2_ELEMS (H_DIM * D_DIM)            // 18432
#define HT_STRIDE 136                         // 128 + 8: float4-aligned row stride
#define SHT_ELEMS (H_DIM * HT_STRIDE)         // 13056
#define SMEM_FLOATS (SW2_ELEMS + SHT_ELEMS + ROWS_PER_CTA + H_DIM + H_DIM + D_DIM)
#define SMEM_BYTES  (SMEM_FLOATS * 4)         // 128000 bytes

__device__ __forceinline__ unsigned long long pack2(float x, float y) {
    unsigned long long r;
    asm("mov.b64 %0, {%1, %2};" : "=l"(r) : "f"(x), "f"(y));
    return r;
}

__device__ __forceinline__ unsigned long long fma2(unsigned long long a,
                                                   unsigned long long b,
                                                   unsigned long long c) {
    unsigned long long d;
    asm("fma.rn.f32x2 %0, %1, %2, %3;" : "=l"(d) : "l"(a), "l"(b), "l"(c));
    return d;
}

__device__ __forceinline__ void cp_async16(float* smem_dst, const float* gsrc) {
    unsigned s = (unsigned)__cvta_generic_to_shared(smem_dst);
    asm volatile("cp.async.cg.shared.global [%0], [%1], 16;" :: "r"(s), "l"(gsrc));
}

__device__ __forceinline__ float gelu_exact(float v) {
    return 0.5f * v * (1.0f + erff(v * 0.70710678118654752f));
}

__global__ __launch_bounds__(THREADS, 1)
void mlp_tokenizer_kernel(const float* __restrict__ x,
                          const float* __restrict__ W1,
                          const float* __restrict__ b1,
                          const float* __restrict__ W2,
                          const float* __restrict__ b2,
                          float* __restrict__ out) {
    extern __shared__ float smem[];
    float* sW2 = smem;                  // [96][192]
    float* sHT = sW2 + SW2_ELEMS;       // [96][136] transposed hidden (k-major)
    float* sX  = sHT + SHT_ELEMS;       // [128]
    float* sW1 = sX  + ROWS_PER_CTA;    // [96]
    float* sB1 = sW1 + H_DIM;           // [96]
    float* sB2 = sB1 + H_DIM;           // [192]

    const int tid = threadIdx.x;
    const int cg  = tid & 15;           // column group: float4 chunks at 4*cg + 64*j
    const int rg  = tid >> 4;           // row group: rows rg*8 .. rg*8+7
    const int HT_STRIDE4 = HT_STRIDE / 4;   // 34

    const int chunk = (N_TILES + gridDim.x - 1) / gridDim.x;
    const int t_beg = blockIdx.x * chunk;
    int t_end = t_beg + chunk;
    if (t_end > N_TILES) t_end = N_TILES;
    if (t_beg >= t_end) return;

    int f_cur = -1;

    // Prefetch x for the first tile.
    float xv = 0.0f;
    {
        const int f0  = t_beg >> 5;
        const int b00 = (t_beg & 31) * ROWS_PER_CTA;
        if (tid < ROWS_PER_CTA) xv = x[(size_t)(b00 + tid) * F_TOTAL + f0];
    }

    for (int t = t_beg; t < t_end; t++) {
        const int f  = t >> 5;          // t / 32
        const int b0 = (t & 31) * ROWS_PER_CTA;

        // ---- Commit prefetched x; stage W2[f] + per-feature vectors on f-change ----
        if (tid < ROWS_PER_CTA) sX[tid] = xv;
        if (f != f_cur) {
            f_cur = f;
            const float* src = W2 + (size_t)f * SW2_ELEMS + tid * 4;
            float* dst = sW2 + tid * 4;
            #pragma unroll
            for (int i = 0; i < SW2_ELEMS / 4 / THREADS; i++)   // 18 iters
                cp_async16(dst + i * (THREADS * 4), src + i * (THREADS * 4));
            asm volatile("cp.async.commit_group;");
            if (tid < H_DIM) {
                sW1[tid] = W1[f * H_DIM + tid];
                sB1[tid] = b1[f * H_DIM + tid];
            }
            if (tid < D_DIM) sB2[tid] = b2[f * D_DIM + tid];
        }
        __syncthreads();   // BAR0: sX (+ sW1/sB1/sB2 on f-change) visible

        // ---- Phase 1: hT[k][row] = gelu(x*W1+b1), float4 in / float4 out ----
        // item i -> k = i/32, row-quad = (i%32)*4. 12 iterations per thread.
        // (overlaps with in-flight cp.async of W2 on f-change iterations)
        for (int i = tid; i < H_DIM * (ROWS_PER_CTA / 4); i += THREADS) {
            int k    = i >> 5;           // / 32
            int row4 = (i & 31) << 2;    // 0,4,...,124
            float w1k = sW1[k], b1k = sB1[k];
            float4 xq = *reinterpret_cast<const float4*>(sX + row4);
            float4 hv;
            hv.x = gelu_exact(fmaf(xq.x, w1k, b1k));
            hv.y = gelu_exact(fmaf(xq.y, w1k, b1k));
            hv.z = gelu_exact(fmaf(xq.z, w1k, b1k));
            hv.w = gelu_exact(fmaf(xq.w, w1k, b1k));
            *reinterpret_cast<float4*>(sHT + k * HT_STRIDE + row4) = hv;
        }

        // ---- Prefetch x for tile t+1 (latency hidden under the GEMM) ----
        if (t + 1 < t_end) {
            const int fn  = (t + 1) >> 5;
            const int b0n = ((t + 1) & 31) * ROWS_PER_CTA;
            if (tid < ROWS_PER_CTA) xv = x[(size_t)(b0n + tid) * F_TOTAL + fn];
        }

        asm volatile("cp.async.wait_group 0;" ::: "memory");  // no-op if none pending
        __syncthreads();   // BAR1: sHT + sW2 visible

        // ---- Phase 2: GEMM, 8 rows x 3 float4 column-chunks per thread ----
        const float* wbase = sW2 + 4 * cg;
        const float4* hbase = reinterpret_cast<const float4*>(sHT + rg * 8);

        ulonglong2 acc[8][3];
        #pragma unroll
        for (int j = 0; j < 3; j++) {
            ulonglong2 bb =
                *reinterpret_cast<const ulonglong2*>(sB2 + 4 * cg + 64 * j);
            #pragma unroll
            for (int r = 0; r < 8; r++) acc[r][j] = bb;
        }

        #pragma unroll 2
        for (int k = 0; k < H_DIM; k++) {
            const float* wk = wbase + k * D_DIM;
            ulonglong2 w[3];
            #pragma unroll
            for (int j = 0; j < 3; j++)
                w[j] = *reinterpret_cast<const ulonglong2*>(wk + 64 * j);

            float4 ha = hbase[k * HT_STRIDE4];
            float4 hb = hbase[k * HT_STRIDE4 + 1];
            unsigned long long hp[8];
            hp[0] = pack2(ha.x, ha.x);  hp[1] = pack2(ha.y, ha.y);
            hp[2] = pack2(ha.z, ha.z);  hp[3] = pack2(ha.w, ha.w);
            hp[4] = pack2(hb.x, hb.x);  hp[5] = pack2(hb.y, hb.y);
            hp[6] = pack2(hb.z, hb.z);  hp[7] = pack2(hb.w, hb.w);

            #pragma unroll
            for (int r = 0; r < 8; r++) {
                #pragma unroll
                for (int j = 0; j < 3; j++) {
                    acc[r][j].x = fma2(hp[r], w[j].x, acc[r][j].x);
                    acc[r][j].y = fma2(hp[r], w[j].y, acc[r][j].y);
                }
            }
        }

        // ---- Epilogue: out[b, f, d], float4 stores (coalesced across cg) ----
        size_t base = ((size_t)(b0 + rg * 8) * F_TOTAL + f) * D_DIM + 4 * cg;
        #pragma unroll
        for (int r = 0; r < 8; r++) {
            float* orow = out + base + (size_t)r * F_TOTAL * D_DIM;
            #pragma unroll
            for (int j = 0; j < 3; j++)
                *reinterpret_cast<ulonglong2*>(orow + 64 * j) = acc[r][j];
        }

        __syncthreads();   // BAR2: protect sHT/sW2/sX/sB2 before next-tile writes
    }
}

extern "C" void kernel_launch(void* const* d_in, const int* in_sizes, int n_in,
                              void* d_out, int out_size) {
    const float* x  = (const float*)d_in[0];
    const float* W1 = (const float*)d_in[1];
    const float* b1 = (const float*)d_in[2];
    const float* W2 = (const float*)d_in[3];
    const float* b2 = (const float*)d_in[4];
    float* out = (float*)d_out;

    static_assert(SMEM_BYTES == 128000, "smem layout changed");
    cudaFuncSetAttribute(mlp_tokenizer_kernel,
                         cudaFuncAttributeMaxDynamicSharedMemorySize, SMEM_BYTES);

    // Host-side query runs during capture only (not replayed) -> no timing cost.
    int nsm = 148;
    cudaDeviceGetAttribute(&nsm, cudaDevAttrMultiProcessorCount, 0);

    mlp_tokenizer_kernel<<<nsm, THREADS, SMEM_BYTES>>>(x, W1, b1, W2, b2, out);
}

// round 17
// speedup vs baseline: 1.1867x; 1.1867x over previous
#include <cuda_runtime.h>
#include <cuda_bf16.h>
#include <cstdint>

// MLPTokenizer: out[b,f,d] = sum_h gelu(x[b,f]*W1[f,h]+b1[f,h]) * W2[f,h,d] + b2[f,d]
// B=4096, F=100, H=96, D=192. fp32, exact GELU (erf).
//
// Persistent-CTA design: grid = #SMs, each CTA processes a contiguous chunk of
// the 3200 (feature, 128-row B-tile) tiles, f-major, so W2[f] (72KB) is staged
// into SMEM at most twice per CTA (cp.async, overlapped with the gelu phase).
// 512 threads (4 warps/SMSP for latency hiding); GEMM register-blocked
// 4 rows x 3 float4 column-chunks per thread on packed fma.rn.f32x2 (FFMA2).

#define B_TOTAL   4096
#define F_TOTAL   100
#define H_DIM     96
#define D_DIM     192
#define ROWS_PER_CTA 128
#define THREADS   512
#define N_BTILES  (B_TOTAL / ROWS_PER_CTA)   // 32
#define N_TILES   (F_TOTAL * N_BTILES)       // 3200

#define SW2_ELEMS (H_DIM * D_DIM)            // 18432
#define HT_STRIDE 136                         // 128 + 8: float4-aligned row stride
#define SHT_ELEMS (H_DIM * HT_STRIDE)         // 13056
#define SMEM_FLOATS (SW2_ELEMS + SHT_ELEMS + ROWS_PER_CTA + H_DIM + H_DIM + D_DIM)
#define SMEM_BYTES  (SMEM_FLOATS * 4)         // 128000 bytes

__device__ __forceinline__ unsigned long long pack2(float x, float y) {
    unsigned long long r;
    asm("mov.b64 %0, {%1, %2};" : "=l"(r) : "f"(x), "f"(y));
    return r;
}

__device__ __forceinline__ unsigned long long fma2(unsigned long long a,
                                                   unsigned long long b,
                                                   unsigned long long c) {
    unsigned long long d;
    asm("fma.rn.f32x2 %0, %1, %2, %3;" : "=l"(d) : "l"(a), "l"(b), "l"(c));
    return d;
}

__device__ __forceinline__ void cp_async16(float* smem_dst, const float* gsrc) {
    unsigned s = (unsigned)__cvta_generic_to_shared(smem_dst);
    asm volatile("cp.async.cg.shared.global [%0], [%1], 16;" :: "r"(s), "l"(gsrc));
}

__device__ __forceinline__ float gelu_exact(float v) {
    return 0.5f * v * (1.0f + erff(v * 0.70710678118654752f));
}

__global__ __launch_bounds__(THREADS, 1)
void mlp_tokenizer_kernel(const float* __restrict__ x,
                          const float* __restrict__ W1,
                          const float* __restrict__ b1,
                          const float* __restrict__ W2,
                          const float* __restrict__ b2,
                          float* __restrict__ out) {
    extern __shared__ float smem[];
    float* sW2 = smem;                  // [96][192]
    float* sHT = sW2 + SW2_ELEMS;       // [96][136] transposed hidden (k-major)
    float* sX  = sHT + SHT_ELEMS;       // [128]
    float* sW1 = sX  + ROWS_PER_CTA;    // [96]
    float* sB1 = sW1 + H_DIM;           // [96]
    float* sB2 = sB1 + H_DIM;           // [192]

    const int tid = threadIdx.x;
    const int cg  = tid & 15;           // column group: float4 chunks at 4*cg + 64*j
    const int rg  = tid >> 4;           // row group [0,32): rows rg*4 .. rg*4+3
    const int HT_STRIDE4 = HT_STRIDE / 4;   // 34

    const int chunk = (N_TILES + gridDim.x - 1) / gridDim.x;
    const int t_beg = blockIdx.x * chunk;
    int t_end = t_beg + chunk;
    if (t_end > N_TILES) t_end = N_TILES;
    if (t_beg >= t_end) return;

    int f_cur = -1;

    // Prefetch x for the first tile.
    float xv = 0.0f;
    {
        const int f0  = t_beg >> 5;
        const int b00 = (t_beg & 31) * ROWS_PER_CTA;
        if (tid < ROWS_PER_CTA) xv = x[(size_t)(b00 + tid) * F_TOTAL + f0];
    }

    for (int t = t_beg; t < t_end; t++) {
        const int f  = t >> 5;          // t / 32
        const int b0 = (t & 31) * ROWS_PER_CTA;

        // ---- Commit prefetched x; stage W2[f] + per-feature vectors on f-change ----
        if (tid < ROWS_PER_CTA) sX[tid] = xv;
        if (f != f_cur) {
            f_cur = f;
            const float* src = W2 + (size_t)f * SW2_ELEMS + tid * 4;
            float* dst = sW2 + tid * 4;
            #pragma unroll
            for (int i = 0; i < SW2_ELEMS / 4 / THREADS; i++)   // 9 iters
                cp_async16(dst + i * (THREADS * 4), src + i * (THREADS * 4));
            asm volatile("cp.async.commit_group;");
            if (tid < H_DIM) {
                sW1[tid] = W1[f * H_DIM + tid];
                sB1[tid] = b1[f * H_DIM + tid];
            }
            if (tid < D_DIM) sB2[tid] = b2[f * D_DIM + tid];
        }
        __syncthreads();   // BAR0: sX (+ sW1/sB1/sB2 on f-change) visible

        // ---- Phase 1: hT[k][row] = gelu(x*W1+b1), float4 in / float4 out ----
        // item i -> k = i/32, row-quad = (i%32)*4. 6 iterations per thread.
        // (overlaps with in-flight cp.async of W2 on f-change iterations)
        for (int i = tid; i < H_DIM * (ROWS_PER_CTA / 4); i += THREADS) {
            int k    = i >> 5;           // / 32
            int row4 = (i & 31) << 2;    // 0,4,...,124
            float w1k = sW1[k], b1k = sB1[k];
            float4 xq = *reinterpret_cast<const float4*>(sX + row4);
            float4 hv;
            hv.x = gelu_exact(fmaf(xq.x, w1k, b1k));
            hv.y = gelu_exact(fmaf(xq.y, w1k, b1k));
            hv.z = gelu_exact(fmaf(xq.z, w1k, b1k));
            hv.w = gelu_exact(fmaf(xq.w, w1k, b1k));
            *reinterpret_cast<float4*>(sHT + k * HT_STRIDE + row4) = hv;
        }

        // ---- Prefetch x for tile t+1 (latency hidden under the GEMM) ----
        if (t + 1 < t_end) {
            const int fn  = (t + 1) >> 5;
            const int b0n = ((t + 1) & 31) * ROWS_PER_CTA;
            if (tid < ROWS_PER_CTA) xv = x[(size_t)(b0n + tid) * F_TOTAL + fn];
        }

        asm volatile("cp.async.wait_group 0;" ::: "memory");  // no-op if none pending
        __syncthreads();   // BAR1: sHT + sW2 visible

        // ---- Phase 2: GEMM, 4 rows x 3 float4 column-chunks per thread ----
        const float* wbase = sW2 + 4 * cg;
        const float4* hbase = reinterpret_cast<const float4*>(sHT + rg * 4);

        ulonglong2 acc[4][3];
        #pragma unroll
        for (int j = 0; j < 3; j++) {
            ulonglong2 bb =
                *reinterpret_cast<const ulonglong2*>(sB2 + 4 * cg + 64 * j);
            #pragma unroll
            for (int r = 0; r < 4; r++) acc[r][j] = bb;
        }

        #pragma unroll 4
        for (int k = 0; k < H_DIM; k++) {
            const float* wk = wbase + k * D_DIM;
            ulonglong2 w[3];
            #pragma unroll
            for (int j = 0; j < 3; j++)
                w[j] = *reinterpret_cast<const ulonglong2*>(wk + 64 * j);

            float4 ha = hbase[k * HT_STRIDE4];
            unsigned long long hp[4];
            hp[0] = pack2(ha.x, ha.x);  hp[1] = pack2(ha.y, ha.y);
            hp[2] = pack2(ha.z, ha.z);  hp[3] = pack2(ha.w, ha.w);

            #pragma unroll
            for (int r = 0; r < 4; r++) {
                #pragma unroll
                for (int j = 0; j < 3; j++) {
                    acc[r][j].x = fma2(hp[r], w[j].x, acc[r][j].x);
                    acc[r][j].y = fma2(hp[r], w[j].y, acc[r][j].y);
                }
            }
        }

        // ---- Epilogue: out[b, f, d], float4 stores (coalesced across cg) ----
        size_t base = ((size_t)(b0 + rg * 4) * F_TOTAL + f) * D_DIM + 4 * cg;
        #pragma unroll
        for (int r = 0; r < 4; r++) {
            float* orow = out + base + (size_t)r * F_TOTAL * D_DIM;
            #pragma unroll
            for (int j = 0; j < 3; j++)
                *reinterpret_cast<ulonglong2*>(orow + 64 * j) = acc[r][j];
        }

        __syncthreads();   // BAR2: protect sHT/sW2/sX/sB2 before next-tile writes
    }
}

extern "C" void kernel_launch(void* const* d_in, const int* in_sizes, int n_in,
                              void* d_out, int out_size) {
    const float* x  = (const float*)d_in[0];
    const float* W1 = (const float*)d_in[1];
    const float* b1 = (const float*)d_in[2];
    const float* W2 = (const float*)d_in[3];
    const float* b2 = (const float*)d_in[4];
    float* out = (float*)d_out;

    static_assert(SMEM_BYTES == 128000, "smem layout changed");
    cudaFuncSetAttribute(mlp_tokenizer_kernel,
                         cudaFuncAttributeMaxDynamicSharedMemorySize, SMEM_BYTES);

    // Host-side query runs during capture only (not replayed) -> no timing cost.
    int nsm = 148;
    cudaDeviceGetAttribute(&nsm, cudaDevAttrMultiProcessorCount, 0);

    mlp_tokenizer_kernel<<<nsm, THREADS, SMEM_BYTES>>>(x, W1, b1, W2, b2, out);
}